// round 7
// baseline (speedup 1.0000x reference)
#include <cuda_runtime.h>
#include <cuda_fp16.h>
#include <cstdint>

// DistMult edge scorer:
//   out[e] = sigmoid( sum_d z[src,d] * rel[rel_id,d] * z[dst,d] )
// Inputs:
//   d_in[0]: z          float32 [100000, 128]
//   d_in[1]: edge_index int32   [2, E]
//   d_in[2]: rel_id     int32   [E]
//   d_in[3]: rel        float32 [64, 128]
// Output: float32 [E]
//
//  1) convert_kernel: z, rel -> fp16 mirrors in __device__ globals.
//  2) distmult_h: rel table (16KB fp16) staged in SMEM per block; z gathered
//     via LDG.128 (8 lanes/edge, 4 edges/pass -> 512B/instr, full lines);
//     rel read via conflict-free LDS.128 (each 8-lane group = 1 phase).
//     Math: HMUL2 x2, cvt, packed add.rn.f32x2; fp32 accumulation.

#define D 128
#define NZ_MAX (100000 * D)
#define NR_MAX (64 * D)
#define FULL 0xFFFFFFFFu

__device__ __half g_zh[NZ_MAX];
__device__ __half g_rh[NR_MAX];

// ---------------- conversion: fp32 -> fp16 mirrors ----------------
__device__ __forceinline__ uint4 cvt8(float4 v0, float4 v1) {
    __half2 h0 = __floats2half2_rn(v0.x, v0.y);
    __half2 h1 = __floats2half2_rn(v0.z, v0.w);
    __half2 h2 = __floats2half2_rn(v1.x, v1.y);
    __half2 h3 = __floats2half2_rn(v1.z, v1.w);
    uint4 o;
    o.x = *reinterpret_cast<unsigned*>(&h0);
    o.y = *reinterpret_cast<unsigned*>(&h1);
    o.z = *reinterpret_cast<unsigned*>(&h2);
    o.w = *reinterpret_cast<unsigned*>(&h3);
    return o;
}

__global__ __launch_bounds__(256) void convert_kernel(
    const float* __restrict__ z, const float* __restrict__ rel,
    int nz, int nr)
{
    int i = blockIdx.x * blockDim.x + threadIdx.x;   // 8 floats per thread
    int nz8 = nz >> 3;
    int nr8 = nr >> 3;
    if (i < nz8) {
        const float4* zp = reinterpret_cast<const float4*>(z);
        reinterpret_cast<uint4*>(g_zh)[i] = cvt8(zp[2 * i], zp[2 * i + 1]);
    } else if (i < nz8 + nr8) {
        int k = i - nz8;
        const float4* rp = reinterpret_cast<const float4*>(rel);
        reinterpret_cast<uint4*>(g_rh)[k] = cvt8(rp[2 * k], rp[2 * k + 1]);
    }
}

// ---------------- main kernel ----------------

// acc2 (packed f32x2) += cvt( (a*c)*b ) for the 2 halves in each word.
__device__ __forceinline__ void dot2p(unsigned a, unsigned c, unsigned b,
                                      unsigned long long& acc2)
{
    __half2 ha = *reinterpret_cast<__half2*>(&a);
    __half2 hc = *reinterpret_cast<__half2*>(&c);
    __half2 hb = *reinterpret_cast<__half2*>(&b);
    __half2 t = __hmul2(ha, hc);
    __half2 u = __hmul2(t, hb);
    float2 uf = __half22float2(u);
    unsigned long long up;
    asm("mov.b64 %0, {%1, %2};" : "=l"(up) : "f"(uf.x), "f"(uf.y));
    asm("add.rn.f32x2 %0, %1, %2;" : "=l"(acc2) : "l"(acc2), "l"(up));
}

__device__ __forceinline__ void dot16p(uint4 a, uint4 c, uint4 b,
                                       unsigned long long& acc2)
{
    dot2p(a.x, c.x, b.x, acc2);
    dot2p(a.y, c.y, b.y, acc2);
    dot2p(a.z, c.z, b.z, acc2);
    dot2p(a.w, c.w, b.w, acc2);
}

__global__ __launch_bounds__(256) void distmult_h(
    const int* __restrict__ edge_index,  // [2, E]
    const int* __restrict__ rel_id,      // [E]
    float* __restrict__ out,
    int E)
{
    // rel table: 64 rows x 256B fp16 = 16KB, staged in SMEM.
    __shared__ uint4 s_rel[64 * 16];     // 16 uint4 per row

    int tid = threadIdx.x;
    {
        const uint4* rh = reinterpret_cast<const uint4*>(g_rh);
        #pragma unroll
        for (int k = 0; k < 4; ++k)      // 256 threads x 4 x 16B = 16KB
            s_rel[tid + k * 256] = rh[tid + k * 256];
    }
    __syncthreads();

    int warp_id = (blockIdx.x * blockDim.x + tid) >> 5;
    int lane = tid & 31;
    int g = lane >> 3;                   // edge group 0..3
    int j = lane & 7;                    // lane within group
    int base = warp_id << 5;             // 32 edges per warp
    if (base >= E) return;

    const uint4* zh = reinterpret_cast<const uint4*>(g_zh);  // 16 uint4 per row

    #pragma unroll 2
    for (int m = 0; m < 8; ++m) {
        int e = base + (m << 2) + g;
        if (e >= E) break;

        // Group-uniform index loads (4 consecutive values per warp instr).
        int s = edge_index[e];
        int d = edge_index[E + e];
        int r = rel_id[e];

        const uint4* zs = zh + (size_t)s * 16;   // 256B row = 16 uint4
        const uint4* zd = zh + (size_t)d * 16;
        const uint4* sr = s_rel + r * 16;

        // z: 4 LDG.128, each instr = 4 full 128B lines.
        uint4 A0 = zs[j], A1 = zs[j + 8];
        uint4 B0 = zd[j], B1 = zd[j + 8];
        // rel: 2 conflict-free LDS.128 (each group = 128 contiguous bytes).
        uint4 C0 = sr[j], C1 = sr[j + 8];

        unsigned long long acc2 = 0ull;          // packed (0.0f, 0.0f)
        dot16p(A0, C0, B0, acc2);
        dot16p(A1, C1, B1, acc2);

        float lo, hi;
        asm("mov.b64 {%0, %1}, %2;" : "=f"(lo), "=f"(hi) : "l"(acc2));
        float acc = lo + hi;

        // Reduce over 8-lane group; 4 edges share the same 3 shfls.
        acc += __shfl_xor_sync(FULL, acc, 4);
        acc += __shfl_xor_sync(FULL, acc, 2);
        acc += __shfl_xor_sync(FULL, acc, 1);

        if (j == 0) {
            // Lanes 0,8,16,24 -> 4 consecutive floats, one wavefront.
            out[e] = 1.0f / (1.0f + __expf(-acc));
        }
    }
}

extern "C" void kernel_launch(void* const* d_in, const int* in_sizes, int n_in,
                              void* d_out, int out_size)
{
    const float* z          = (const float*)d_in[0];
    const int*   edge_index = (const int*)d_in[1];
    const int*   rel_id     = (const int*)d_in[2];
    const float* rel        = (const float*)d_in[3];
    float*       out        = (float*)d_out;

    int nz = in_sizes[0];            // z element count (<= NZ_MAX)
    int nr = in_sizes[3];            // rel element count
    int E  = in_sizes[2];

    if (nz > NZ_MAX) nz = NZ_MAX;
    if (nr > NR_MAX) nr = NR_MAX;

    // 1) fp32 -> fp16 mirrors (8 floats per thread, 16B stores)
    {
        int work = (nz >> 3) + (nr >> 3);
        int threads = 256;
        int blocks = (work + threads - 1) / threads;
        convert_kernel<<<blocks, threads>>>(z, rel, nz, nr);
    }

    // 2) edge scoring
    {
        const int threads = 256;                 // 8 warps/block, 32 edges/warp
        int edges_per_block = (threads / 32) * 32;
        int blocks = (E + edges_per_block - 1) / edges_per_block;
        distmult_h<<<blocks, threads>>>(edge_index, rel_id, out, E);
    }
}

// round 8
// speedup vs baseline: 1.0911x; 1.0911x over previous
#include <cuda_runtime.h>
#include <cuda_fp16.h>
#include <cstdint>

// DistMult edge scorer:
//   out[e] = sigmoid( sum_d z[src,d] * rel[rel_id,d] * z[dst,d] )
// Inputs:
//   d_in[0]: z          float32 [100000, 128]
//   d_in[1]: edge_index int32   [2, E]
//   d_in[2]: rel_id     int32   [E]
//   d_in[3]: rel        float32 [64, 128]
// Output: float32 [E]
//
//  1) convert_kernel: z, rel -> fp16 mirrors (__device__ globals), 8 floats
//     per thread, single 16B store (fastest measured variant).
//  2) distmult_h: 8 lanes/edge, 4 edges/warp-pass; fp16 rows = 256B; every
//     LDG.128 covers 4 full 128B lines. Math: HMUL2(src,rel) -> cvt -> fp32
//     FFMA with dst (fastest measured variant). unroll 4 for deep MLP.

#define D 128
#define NZ_MAX (100000 * D)
#define NR_MAX (64 * D)
#define FULL 0xFFFFFFFFu

__device__ __half g_zh[NZ_MAX];
__device__ __half g_rh[NR_MAX];

// ---------------- conversion: fp32 -> fp16 mirrors ----------------
__device__ __forceinline__ uint4 cvt8(float4 v0, float4 v1) {
    __half2 h0 = __floats2half2_rn(v0.x, v0.y);
    __half2 h1 = __floats2half2_rn(v0.z, v0.w);
    __half2 h2 = __floats2half2_rn(v1.x, v1.y);
    __half2 h3 = __floats2half2_rn(v1.z, v1.w);
    uint4 o;
    o.x = *reinterpret_cast<unsigned*>(&h0);
    o.y = *reinterpret_cast<unsigned*>(&h1);
    o.z = *reinterpret_cast<unsigned*>(&h2);
    o.w = *reinterpret_cast<unsigned*>(&h3);
    return o;
}

__global__ __launch_bounds__(256) void convert_kernel(
    const float* __restrict__ z, const float* __restrict__ rel,
    int nz, int nr)
{
    int i = blockIdx.x * blockDim.x + threadIdx.x;   // 8 floats per thread
    int nz8 = nz >> 3;
    int nr8 = nr >> 3;
    if (i < nz8) {
        const float4* zp = reinterpret_cast<const float4*>(z);
        reinterpret_cast<uint4*>(g_zh)[i] = cvt8(zp[2 * i], zp[2 * i + 1]);
    } else if (i < nz8 + nr8) {
        int k = i - nz8;
        const float4* rp = reinterpret_cast<const float4*>(rel);
        reinterpret_cast<uint4*>(g_rh)[k] = cvt8(rp[2 * k], rp[2 * k + 1]);
    }
}

// ---------------- main kernel ----------------

// acc += sum over the 2 halves packed in (a,c,b): fp16 mul src*rel, then
// fp32 FMA with dst. (R5 form: ptxas schedules this best.)
__device__ __forceinline__ float dot2(unsigned a, unsigned c, unsigned b, float acc)
{
    __half2 ha = *reinterpret_cast<__half2*>(&a);
    __half2 hc = *reinterpret_cast<__half2*>(&c);
    __half2 hb = *reinterpret_cast<__half2*>(&b);
    __half2 t  = __hmul2(ha, hc);
    float2 tf = __half22float2(t);
    float2 bf = __half22float2(hb);
    acc = fmaf(tf.x, bf.x, acc);
    acc = fmaf(tf.y, bf.y, acc);
    return acc;
}

__device__ __forceinline__ float dot16(uint4 a, uint4 c, uint4 b, float acc)
{
    acc = dot2(a.x, c.x, b.x, acc);
    acc = dot2(a.y, c.y, b.y, acc);
    acc = dot2(a.z, c.z, b.z, acc);
    acc = dot2(a.w, c.w, b.w, acc);
    return acc;
}

__global__ __launch_bounds__(256) void distmult_h(
    const int* __restrict__ edge_index,  // [2, E]
    const int* __restrict__ rel_id,      // [E]
    float* __restrict__ out,
    int E)
{
    int warp_id = (blockIdx.x * blockDim.x + threadIdx.x) >> 5;
    int lane = threadIdx.x & 31;
    int g = lane >> 3;                   // edge group 0..3
    int j = lane & 7;                    // lane within group
    int base = warp_id << 5;             // 32 edges per warp
    if (base >= E) return;

    const uint4* zh = reinterpret_cast<const uint4*>(g_zh);  // 16 uint4 per row
    const uint4* rh = reinterpret_cast<const uint4*>(g_rh);

    #pragma unroll 4
    for (int m = 0; m < 8; ++m) {
        int e = base + (m << 2) + g;
        if (e >= E) break;

        // Group-uniform index loads (4 consecutive values per warp instr).
        int s = edge_index[e];
        int d = edge_index[E + e];
        int r = rel_id[e];

        const uint4* zs = zh + (size_t)s * 16;   // 256B row = 16 uint4
        const uint4* zd = zh + (size_t)d * 16;
        const uint4* rr = rh + (size_t)r * 16;

        // 6 independent 16B loads; each warp instr = 4 full 128B lines.
        uint4 A0 = zs[j], A1 = zs[j + 8];
        uint4 B0 = zd[j], B1 = zd[j + 8];
        uint4 C0 = rr[j], C1 = rr[j + 8];

        float acc = 0.0f;
        acc = dot16(A0, C0, B0, acc);
        acc = dot16(A1, C1, B1, acc);

        // Reduce over 8-lane group; 4 edges share the same 3 shfls.
        acc += __shfl_xor_sync(FULL, acc, 4);
        acc += __shfl_xor_sync(FULL, acc, 2);
        acc += __shfl_xor_sync(FULL, acc, 1);

        if (j == 0) {
            // Lanes 0,8,16,24 -> 4 consecutive floats, one wavefront.
            out[e] = 1.0f / (1.0f + __expf(-acc));
        }
    }
}

extern "C" void kernel_launch(void* const* d_in, const int* in_sizes, int n_in,
                              void* d_out, int out_size)
{
    const float* z          = (const float*)d_in[0];
    const int*   edge_index = (const int*)d_in[1];
    const int*   rel_id     = (const int*)d_in[2];
    const float* rel        = (const float*)d_in[3];
    float*       out        = (float*)d_out;

    int nz = in_sizes[0];            // z element count (<= NZ_MAX)
    int nr = in_sizes[3];            // rel element count
    int E  = in_sizes[2];

    if (nz > NZ_MAX) nz = NZ_MAX;
    if (nr > NR_MAX) nr = NR_MAX;

    // 1) fp32 -> fp16 mirrors (8 floats per thread, one 16B store)
    {
        int work = (nz >> 3) + (nr >> 3);
        int threads = 256;
        int blocks = (work + threads - 1) / threads;
        convert_kernel<<<blocks, threads>>>(z, rel, nz, nr);
    }

    // 2) edge scoring
    {
        const int threads = 256;                 // 8 warps/block, 32 edges/warp
        int edges_per_block = (threads / 32) * 32;
        int blocks = (E + edges_per_block - 1) / edges_per_block;
        distmult_h<<<blocks, threads>>>(edge_index, rel_id, out, E);
    }
}

// round 9
// speedup vs baseline: 1.1491x; 1.0532x over previous
#include <cuda_runtime.h>
#include <cuda_fp16.h>
#include <cstdint>

// DistMult edge scorer:
//   out[e] = sigmoid( sum_d z[src,d] * rel[rel_id,d] * z[dst,d] )
// Inputs:
//   d_in[0]: z          float32 [100000, 128]
//   d_in[1]: edge_index int32   [2, E]
//   d_in[2]: rel_id     int32   [E]
//   d_in[3]: rel        float32 [64, 128]
// Output: float32 [E]
//
// Best-of recombination (measured across rounds):
//  1) convert_kernel (R6 variant, 7.1us): 8 floats/thread, one 16B store.
//  2) distmult_h (R5 variant, 73.2us): 8 lanes/edge, 4 edges/warp-pass,
//     unroll 2, HMUL2(src,rel) -> cvt -> fp32 FFMA with dst, 32 regs,
//     occ ~90%. Every LDG.128 covers 4 full 128B lines.

#define D 128
#define NZ_MAX (100000 * D)
#define NR_MAX (64 * D)
#define FULL 0xFFFFFFFFu

__device__ __half g_zh[NZ_MAX];
__device__ __half g_rh[NR_MAX];

// ---------------- conversion: fp32 -> fp16 mirrors (R6 variant) ----------------
__device__ __forceinline__ uint4 cvt8(float4 v0, float4 v1) {
    __half2 h0 = __floats2half2_rn(v0.x, v0.y);
    __half2 h1 = __floats2half2_rn(v0.z, v0.w);
    __half2 h2 = __floats2half2_rn(v1.x, v1.y);
    __half2 h3 = __floats2half2_rn(v1.z, v1.w);
    uint4 o;
    o.x = *reinterpret_cast<unsigned*>(&h0);
    o.y = *reinterpret_cast<unsigned*>(&h1);
    o.z = *reinterpret_cast<unsigned*>(&h2);
    o.w = *reinterpret_cast<unsigned*>(&h3);
    return o;
}

__global__ __launch_bounds__(256) void convert_kernel(
    const float* __restrict__ z, const float* __restrict__ rel,
    int nz, int nr)
{
    int i = blockIdx.x * blockDim.x + threadIdx.x;   // 8 floats per thread
    int nz8 = nz >> 3;
    int nr8 = nr >> 3;
    if (i < nz8) {
        const float4* zp = reinterpret_cast<const float4*>(z);
        reinterpret_cast<uint4*>(g_zh)[i] = cvt8(zp[2 * i], zp[2 * i + 1]);
    } else if (i < nz8 + nr8) {
        int k = i - nz8;
        const float4* rp = reinterpret_cast<const float4*>(rel);
        reinterpret_cast<uint4*>(g_rh)[k] = cvt8(rp[2 * k], rp[2 * k + 1]);
    }
}

// ---------------- main kernel (R5 variant) ----------------

// acc += sum over the 2 halves packed in (a,c,b): fp16 mul src*rel, then
// fp32 FMA with dst.
__device__ __forceinline__ float dot2(unsigned a, unsigned c, unsigned b, float acc)
{
    __half2 ha = *reinterpret_cast<__half2*>(&a);
    __half2 hc = *reinterpret_cast<__half2*>(&c);
    __half2 hb = *reinterpret_cast<__half2*>(&b);
    __half2 t  = __hmul2(ha, hc);
    float2 tf = __half22float2(t);
    float2 bf = __half22float2(hb);
    acc = fmaf(tf.x, bf.x, acc);
    acc = fmaf(tf.y, bf.y, acc);
    return acc;
}

__device__ __forceinline__ float dot16(uint4 a, uint4 c, uint4 b, float acc)
{
    acc = dot2(a.x, c.x, b.x, acc);
    acc = dot2(a.y, c.y, b.y, acc);
    acc = dot2(a.z, c.z, b.z, acc);
    acc = dot2(a.w, c.w, b.w, acc);
    return acc;
}

__global__ __launch_bounds__(256) void distmult_h(
    const int* __restrict__ edge_index,  // [2, E]
    const int* __restrict__ rel_id,      // [E]
    float* __restrict__ out,
    int E)
{
    int warp_id = (blockIdx.x * blockDim.x + threadIdx.x) >> 5;
    int lane = threadIdx.x & 31;
    int g = lane >> 3;                   // edge group 0..3
    int j = lane & 7;                    // lane within group
    int base = warp_id << 5;             // 32 edges per warp
    if (base >= E) return;

    const uint4* zh = reinterpret_cast<const uint4*>(g_zh);  // 16 uint4 per row
    const uint4* rh = reinterpret_cast<const uint4*>(g_rh);

    #pragma unroll 2
    for (int m = 0; m < 8; ++m) {
        int e = base + (m << 2) + g;
        if (e >= E) break;

        // Group-uniform index loads (4 consecutive values per warp instr).
        int s = edge_index[e];
        int d = edge_index[E + e];
        int r = rel_id[e];

        const uint4* zs = zh + (size_t)s * 16;   // 256B row = 16 uint4
        const uint4* zd = zh + (size_t)d * 16;
        const uint4* rr = rh + (size_t)r * 16;

        // 6 independent 16B loads; each warp instr = 4 full 128B lines.
        uint4 A0 = zs[j], A1 = zs[j + 8];
        uint4 B0 = zd[j], B1 = zd[j + 8];
        uint4 C0 = rr[j], C1 = rr[j + 8];

        float acc = 0.0f;
        acc = dot16(A0, C0, B0, acc);
        acc = dot16(A1, C1, B1, acc);

        // Reduce over 8-lane group; 4 edges share the same 3 shfls.
        acc += __shfl_xor_sync(FULL, acc, 4);
        acc += __shfl_xor_sync(FULL, acc, 2);
        acc += __shfl_xor_sync(FULL, acc, 1);

        if (j == 0) {
            // Lanes 0,8,16,24 -> 4 consecutive floats, one wavefront.
            out[e] = 1.0f / (1.0f + __expf(-acc));
        }
    }
}

extern "C" void kernel_launch(void* const* d_in, const int* in_sizes, int n_in,
                              void* d_out, int out_size)
{
    const float* z          = (const float*)d_in[0];
    const int*   edge_index = (const int*)d_in[1];
    const int*   rel_id     = (const int*)d_in[2];
    const float* rel        = (const float*)d_in[3];
    float*       out        = (float*)d_out;

    int nz = in_sizes[0];            // z element count (<= NZ_MAX)
    int nr = in_sizes[3];            // rel element count
    int E  = in_sizes[2];

    if (nz > NZ_MAX) nz = NZ_MAX;
    if (nr > NR_MAX) nr = NR_MAX;

    // 1) fp32 -> fp16 mirrors (8 floats per thread, one 16B store)
    {
        int work = (nz >> 3) + (nr >> 3);
        int threads = 256;
        int blocks = (work + threads - 1) / threads;
        convert_kernel<<<blocks, threads>>>(z, rel, nz, nr);
    }

    // 2) edge scoring
    {
        const int threads = 256;                 // 8 warps/block, 32 edges/warp
        int edges_per_block = (threads / 32) * 32;
        int blocks = (E + edges_per_block - 1) / edges_per_block;
        distmult_h<<<blocks, threads>>>(edge_index, rel_id, out, E);
    }
}

// round 10
// speedup vs baseline: 1.2053x; 1.0489x over previous
#include <cuda_runtime.h>
#include <cuda_fp16.h>
#include <cstdint>

// DistMult edge scorer:
//   out[e] = sigmoid( sum_d z[src,d] * rel[rel_id,d] * z[dst,d] )
// Inputs:
//   d_in[0]: z          float32 [100000, 128]
//   d_in[1]: edge_index int32   [2, E]
//   d_in[2]: rel_id     int32   [E]
//   d_in[3]: rel        float32 [64, 128]
// Output: float32 [E]
//
//  1) convert_kernel: z, rel -> fp16 mirrors (8 floats/thread, one 16B store).
//  2) distmult_h: 8 lanes/edge, 4 edges/warp-pass, unroll 2 (R5 shape).
//     Math: HFMA2 accumulation into 4 INDEPENDENT half2 accumulators
//     (2 instr / 2 dims, dep chains of length 2), pairwise HADD2, fp32
//     epilogue + fp32 shfl reduction. Cuts flop instrs 56 -> 25 per
//     lane-pass to unclog the issue stage; loads unchanged.

#define D 128
#define NZ_MAX (100000 * D)
#define NR_MAX (64 * D)
#define FULL 0xFFFFFFFFu

__device__ __half g_zh[NZ_MAX];
__device__ __half g_rh[NR_MAX];

// ---------------- conversion: fp32 -> fp16 mirrors ----------------
__device__ __forceinline__ uint4 cvt8(float4 v0, float4 v1) {
    __half2 h0 = __floats2half2_rn(v0.x, v0.y);
    __half2 h1 = __floats2half2_rn(v0.z, v0.w);
    __half2 h2 = __floats2half2_rn(v1.x, v1.y);
    __half2 h3 = __floats2half2_rn(v1.z, v1.w);
    uint4 o;
    o.x = *reinterpret_cast<unsigned*>(&h0);
    o.y = *reinterpret_cast<unsigned*>(&h1);
    o.z = *reinterpret_cast<unsigned*>(&h2);
    o.w = *reinterpret_cast<unsigned*>(&h3);
    return o;
}

__global__ __launch_bounds__(256) void convert_kernel(
    const float* __restrict__ z, const float* __restrict__ rel,
    int nz, int nr)
{
    int i = blockIdx.x * blockDim.x + threadIdx.x;   // 8 floats per thread
    int nz8 = nz >> 3;
    int nr8 = nr >> 3;
    if (i < nz8) {
        const float4* zp = reinterpret_cast<const float4*>(z);
        reinterpret_cast<uint4*>(g_zh)[i] = cvt8(zp[2 * i], zp[2 * i + 1]);
    } else if (i < nz8 + nr8) {
        int k = i - nz8;
        const float4* rp = reinterpret_cast<const float4*>(rel);
        reinterpret_cast<uint4*>(g_rh)[k] = cvt8(rp[2 * k], rp[2 * k + 1]);
    }
}

// ---------------- main kernel ----------------

__device__ __forceinline__ __half2 h2_of(unsigned u) {
    return *reinterpret_cast<__half2*>(&u);
}

__global__ __launch_bounds__(256) void distmult_h(
    const int* __restrict__ edge_index,  // [2, E]
    const int* __restrict__ rel_id,      // [E]
    float* __restrict__ out,
    int E)
{
    int warp_id = (blockIdx.x * blockDim.x + threadIdx.x) >> 5;
    int lane = threadIdx.x & 31;
    int g = lane >> 3;                   // edge group 0..3
    int j = lane & 7;                    // lane within group
    int base = warp_id << 5;             // 32 edges per warp
    if (base >= E) return;

    const uint4* zh = reinterpret_cast<const uint4*>(g_zh);  // 16 uint4 per row
    const uint4* rh = reinterpret_cast<const uint4*>(g_rh);

    #pragma unroll 2
    for (int m = 0; m < 8; ++m) {
        int e = base + (m << 2) + g;
        if (e >= E) break;

        // Group-uniform index loads (4 consecutive values per warp instr).
        int s = edge_index[e];
        int d = edge_index[E + e];
        int r = rel_id[e];

        const uint4* zs = zh + (size_t)s * 16;   // 256B row = 16 uint4
        const uint4* zd = zh + (size_t)d * 16;
        const uint4* rr = rh + (size_t)r * 16;

        // 6 independent 16B loads; each warp instr = 4 full 128B lines.
        uint4 A0 = zs[j], A1 = zs[j + 8];
        uint4 B0 = zd[j], B1 = zd[j + 8];
        uint4 C0 = rr[j], C1 = rr[j + 8];

        // 4 independent half2 accumulators; 2 terms each.
        __half2 acc0 = __hmul2(__hmul2(h2_of(A0.x), h2_of(C0.x)), h2_of(B0.x));
        __half2 acc1 = __hmul2(__hmul2(h2_of(A0.y), h2_of(C0.y)), h2_of(B0.y));
        __half2 acc2 = __hmul2(__hmul2(h2_of(A0.z), h2_of(C0.z)), h2_of(B0.z));
        __half2 acc3 = __hmul2(__hmul2(h2_of(A0.w), h2_of(C0.w)), h2_of(B0.w));
        acc0 = __hfma2(__hmul2(h2_of(A1.x), h2_of(C1.x)), h2_of(B1.x), acc0);
        acc1 = __hfma2(__hmul2(h2_of(A1.y), h2_of(C1.y)), h2_of(B1.y), acc1);
        acc2 = __hfma2(__hmul2(h2_of(A1.z), h2_of(C1.z)), h2_of(B1.z), acc2);
        acc3 = __hfma2(__hmul2(h2_of(A1.w), h2_of(C1.w)), h2_of(B1.w), acc3);

        // Pairwise fp16 combine, then fp32 epilogue.
        __half2 s01 = __hadd2(acc0, acc1);
        __half2 s23 = __hadd2(acc2, acc3);
        float2 f01 = __half22float2(s01);
        float2 f23 = __half22float2(s23);
        float acc = (f01.x + f01.y) + (f23.x + f23.y);

        // Reduce over 8-lane group (fp32); 4 edges share the same 3 shfls.
        acc += __shfl_xor_sync(FULL, acc, 4);
        acc += __shfl_xor_sync(FULL, acc, 2);
        acc += __shfl_xor_sync(FULL, acc, 1);

        if (j == 0) {
            // Lanes 0,8,16,24 -> 4 consecutive floats, one wavefront.
            out[e] = 1.0f / (1.0f + __expf(-acc));
        }
    }
}

extern "C" void kernel_launch(void* const* d_in, const int* in_sizes, int n_in,
                              void* d_out, int out_size)
{
    const float* z          = (const float*)d_in[0];
    const int*   edge_index = (const int*)d_in[1];
    const int*   rel_id     = (const int*)d_in[2];
    const float* rel        = (const float*)d_in[3];
    float*       out        = (float*)d_out;

    int nz = in_sizes[0];            // z element count (<= NZ_MAX)
    int nr = in_sizes[3];            // rel element count
    int E  = in_sizes[2];

    if (nz > NZ_MAX) nz = NZ_MAX;
    if (nr > NR_MAX) nr = NR_MAX;

    // 1) fp32 -> fp16 mirrors (8 floats per thread, one 16B store)
    {
        int work = (nz >> 3) + (nr >> 3);
        int threads = 256;
        int blocks = (work + threads - 1) / threads;
        convert_kernel<<<blocks, threads>>>(z, rel, nz, nr);
    }

    // 2) edge scoring
    {
        const int threads = 256;                 // 8 warps/block, 32 edges/warp
        int edges_per_block = (threads / 32) * 32;
        int blocks = (E + edges_per_block - 1) / edges_per_block;
        distmult_h<<<blocks, threads>>>(edge_index, rel_id, out, E);
    }
}